// round 5
// baseline (speedup 1.0000x reference)
#include <cuda_runtime.h>
#include <cstdint>

#define BB 128
#define CC 32
#define LL 4096
#define LT 16           // l positions per CTA
#define BCH 8           // batch rows per chunk
#define NCH 4           // chunks per CTA (32 b per CTA)
#define BSPLIT 4        // b-splits across CTAs
#define THREADS 512     // 16 warps, warp w handles l = l0 + w

#define XS_FLOATS (BCH * LT * CC)     // 4096 floats per buffer
#define OS_PAD 17
#define OS_FLOATS (BCH * CC * OS_PAD) // 4352

__device__ __forceinline__ unsigned long long pack_f32x2(float lo, float hi) {
    unsigned long long r;
    asm("mov.b64 %0, {%1, %2};" : "=l"(r) : "r"(__float_as_uint(lo)), "r"(__float_as_uint(hi)));
    return r;
}
__device__ __forceinline__ void unpack_f32x2(unsigned long long v, float& lo, float& hi) {
    unsigned int a, b;
    asm("mov.b64 {%0, %1}, %2;" : "=r"(a), "=r"(b) : "l"(v));
    lo = __uint_as_float(a);
    hi = __uint_as_float(b);
}
__device__ __forceinline__ void fma2(unsigned long long& d, unsigned long long a,
                                     unsigned long long b, unsigned long long c) {
    asm("fma.rn.f32x2 %0, %1, %2, %3;" : "=l"(d) : "l"(a), "l"(b), "l"(c));
}
__device__ __forceinline__ unsigned long long add2(unsigned long long a, unsigned long long b) {
    unsigned long long d;
    asm("add.rn.f32x2 %0, %1, %2;" : "=l"(d) : "l"(a), "l"(b));
    return d;
}

__global__ void __launch_bounds__(THREADS, 2)
dyna_dec_kernel(const float* __restrict__ x, const float* __restrict__ weight,
                const float* __restrict__ bias, float* __restrict__ out) {
    __shared__ __align__(16) float x_s[2][XS_FLOATS];   // double-buffered
    __shared__ __align__(16) float o_s[OS_FLOATS];

    const int tid  = threadIdx.x;
    const int w    = tid >> 5;       // warp index = local l
    const int lane = tid & 31;       // output channel d (compute phase)
    const int l0   = blockIdx.x * LT;
    const int b0   = blockIdx.y * (BCH * NCH);
    const int lg   = l0 + w;

    // ---------- prologue: issue x prefetch FIRST (longest pole) ----------
    float4 pf0, pf1;
    {
        int t0 = tid,           ls0 = t0 & 3, r0 = t0 >> 2;
        int t1 = THREADS + tid, ls1 = t1 & 3, r1 = t1 >> 2;
        pf0 = *(const float4*)(x + ((size_t)((b0 + (r0 >> 5)) * CC + (r0 & 31))) * LL + l0 + 4 * ls0);
        pf1 = *(const float4*)(x + ((size_t)((b0 + (r1 >> 5)) * CC + (r1 & 31))) * LL + l0 + 4 * ls1);
    }

    // ---- Per-warp weight column: W2[p] = {W[lg][2p][lane], W[lg][2p+1][lane]} ----
    // Issued after pf; consumed only at first compute (latency hidden by stage+sync).
    unsigned long long W2[CC / 2];
    {
        const float* wp = weight + (size_t)lg * CC * CC + lane;
        #pragma unroll
        for (int p = 0; p < CC / 2; p++) {
            float a = __ldg(wp + (2 * p) * CC);
            float b = __ldg(wp + (2 * p + 1) * CC);
            W2[p] = pack_f32x2(a, b);
        }
    }
    const float bi = __ldg(bias + lg * CC + lane);

    const int swc = (w >> 1) & 6;    // compute-side x_s chunk swizzle for l = w
    const int seg = w >> 2, j = w & 3;

    #pragma unroll
    for (int ch = 0; ch < NCH; ch++) {
        float* xb = x_s[ch & 1];

        // ---- stage prefetched chunk into x_s[parity] (swizzled, conflict-free) ----
        #pragma unroll
        for (int it = 0; it < 2; it++) {
            int t = it * THREADS + tid;
            int lseg = t & 3;
            int r = t >> 2;
            int b = r >> 5, c = r & 31;
            int slot = ((c >> 2) ^ (2 * lseg)) & 7;
            float* dst = xb + b * (LT * CC) + (4 * lseg) * CC + slot * 4 + (c & 3);
            float4 v = it == 0 ? pf0 : pf1;
            dst[0 * CC] = v.x; dst[1 * CC] = v.y; dst[2 * CC] = v.z; dst[3 * CC] = v.w;
        }

        // ---- prefetch next chunk (latency covered by compute + out phases) ----
        if (ch + 1 < NCH) {
            int bc = b0 + (ch + 1) * BCH;
            int t0 = tid,           ls0 = t0 & 3, r0 = t0 >> 2;
            int t1 = THREADS + tid, ls1 = t1 & 3, r1 = t1 >> 2;
            pf0 = *(const float4*)(x + ((size_t)((bc + (r0 >> 5)) * CC + (r0 & 31))) * LL + l0 + 4 * ls0);
            pf1 = *(const float4*)(x + ((size_t)((bc + (r1 >> 5)) * CC + (r1 & 31))) * LL + l0 + 4 * ls1);
        }

        __syncthreads();  // x_s[parity] ready; everyone past out-pass of ch-1 (o_s free)

        // ---- compute: warp w handles l = l0 + w; lane = d; 4 accumulators ----
        #pragma unroll
        for (int b = 0; b < BCH; b++) {
            const char* base = (const char*)(xb + b * (LT * CC) + w * CC);
            unsigned long long a0 = 0ull, a1 = 0ull, a2 = 0ull, a3 = 0ull;
            #pragma unroll
            for (int u = 0; u < 8; u += 2) {
                ulonglong2 v0 = *(const ulonglong2*)(base + ((( u      ^ swc) & 7) << 4));
                ulonglong2 v1 = *(const ulonglong2*)(base + ((((u + 1) ^ swc) & 7) << 4));
                fma2(a0, v0.x, W2[2 * u + 0], a0);
                fma2(a1, v0.y, W2[2 * u + 1], a1);
                fma2(a2, v1.x, W2[2 * u + 2], a2);
                fma2(a3, v1.y, W2[2 * u + 3], a3);
            }
            unsigned long long s = add2(add2(a0, a1), add2(a2, a3));
            float lo, hi;
            unpack_f32x2(s, lo, hi);
            int row = b * CC + lane;
            int segp = (seg + ((row >> 1) & 2)) & 3;          // additive seg swizzle
            o_s[row * OS_PAD + 4 * segp + j] = lo + hi + bi;  // conflict-free STS
        }
        __syncthreads();  // o_s ready

        // ---- output pass: gather rows from o_s, vectorized STG ----
        #pragma unroll
        for (int it = 0; it < 2; it++) {
            int t = it * THREADS + tid;
            int s = t & 3;
            int r = t >> 2;                 // row = b*32 + d
            int b = r >> 5, d = r & 31;
            int segp = (s + ((r >> 1) & 2)) & 3;
            const float* src = o_s + r * OS_PAD + 4 * segp;
            float4 v;
            v.x = src[0]; v.y = src[1]; v.z = src[2]; v.w = src[3];
            *(float4*)(out + ((size_t)((b0 + ch * BCH + b) * CC + d)) * LL + l0 + 4 * s) = v;
        }
        // no third sync: next stage writes the OTHER x_s buffer; next compute's
        // o_s writes are fenced by the sync at the top of the next iteration.
    }
}

extern "C" void kernel_launch(void* const* d_in, const int* in_sizes, int n_in,
                              void* d_out, int out_size) {
    const float* x      = (const float*)d_in[0];
    // d_in[1] = px, unused by the reference
    const float* weight = (const float*)d_in[2];
    const float* bias   = (const float*)d_in[3];
    float* out          = (float*)d_out;

    dim3 grid(LL / LT, BSPLIT);   // (256, 4) = 1024 CTAs
    dim3 block(THREADS);
    dyna_dec_kernel<<<grid, block>>>(x, weight, bias, out);
}